// round 1
// baseline (speedup 1.0000x reference)
#include <cuda_runtime.h>
#include <cuda_bf16.h>
#include <stdint.h>

#define S_LEN 4096
#define D_MODEL 2048
#define D_CQ 1536
#define H 8
#define D 128
#define NEG (-1000000000.0f)
#define HAD_SCALE 0.08838834764831845f   // 128^-0.5 (also D^-0.5)

// scratch (device globals; no allocation allowed)
__device__ __nv_bfloat16 g_qprime[S_LEN * H * D];   // [t][h][d] bf16, 8 MB
__device__ __nv_bfloat16 g_kprime[S_LEN * D];       // [s][d]    bf16, 1 MB
__device__ float         g_w[S_LEN * H];            // [t][h]    f32

__device__ __forceinline__ void mma16816(float c[4], const uint32_t a[4], const uint32_t b[2]) {
    asm volatile(
        "mma.sync.aligned.m16n8k16.row.col.f32.bf16.bf16.f32 "
        "{%0,%1,%2,%3}, {%4,%5,%6,%7}, {%8,%9}, {%0,%1,%2,%3};\n"
        : "+f"(c[0]), "+f"(c[1]), "+f"(c[2]), "+f"(c[3])
        : "r"(a[0]), "r"(a[1]), "r"(a[2]), "r"(a[3]), "r"(b[0]), "r"(b[1]));
}

// ---------------------------------------------------------------------------
// Kernel 1: q = rope+hadamard(q_latent @ Wq), one head (128 cols) per CTA.
// grid (H, 64), 256 threads. BM=64, BN=128, BK=32.
// ---------------------------------------------------------------------------
__global__ __launch_bounds__(256) void qproj_kernel(const float* __restrict__ qlat,
                                                    const float* __restrict__ Wq) {
    const int h  = blockIdx.x;
    const int t0 = blockIdx.y * 64;
    __shared__ __nv_bfloat16 As[64][40];    // 80B row stride -> 20-word bank shift, conflict-free frags
    __shared__ __nv_bfloat16 Bs[128][40];   // stored [n][k]
    __shared__ float Es[64][129];
    const int tid  = threadIdx.x;
    const int lane = tid & 31, warp = tid >> 5;
    const int wm = (warp & 3) * 16;         // 4 m-warps
    const int wn = (warp >> 2) * 64;        // 2 n-warps, 64 cols each
    const int gid = lane >> 2, tig = lane & 3;
    const int n0 = h * 128;

    float acc[8][4];
    #pragma unroll
    for (int i = 0; i < 8; i++)
        #pragma unroll
        for (int j = 0; j < 4; j++) acc[i][j] = 0.f;

    for (int k0 = 0; k0 < D_CQ; k0 += 32) {
        #pragma unroll
        for (int i = 0; i < 8; i++) {               // As: 64x32
            int idx = tid + i * 256;
            int r = idx >> 5, c = idx & 31;
            As[r][c] = __float2bfloat16(qlat[(size_t)(t0 + r) * D_CQ + k0 + c]);
        }
        #pragma unroll
        for (int i = 0; i < 16; i++) {              // Bs: 32x128 transposed -> [n][k]
            int idx = tid + i * 256;
            int kk = idx >> 7, n = idx & 127;
            Bs[n][kk] = __float2bfloat16(Wq[(size_t)(k0 + kk) * (H * D) + n0 + n]);
        }
        __syncthreads();
        #pragma unroll
        for (int kc = 0; kc < 32; kc += 16) {
            uint32_t a[4];
            a[0] = *(const uint32_t*)&As[wm + gid    ][kc + 2 * tig];
            a[1] = *(const uint32_t*)&As[wm + gid + 8][kc + 2 * tig];
            a[2] = *(const uint32_t*)&As[wm + gid    ][kc + 2 * tig + 8];
            a[3] = *(const uint32_t*)&As[wm + gid + 8][kc + 2 * tig + 8];
            #pragma unroll
            for (int nt = 0; nt < 8; nt++) {
                uint32_t b[2];
                b[0] = *(const uint32_t*)&Bs[wn + nt * 8 + gid][kc + 2 * tig];
                b[1] = *(const uint32_t*)&Bs[wn + nt * 8 + gid][kc + 2 * tig + 8];
                mma16816(acc[nt], a, b);
            }
        }
        __syncthreads();
    }
    // scatter accum -> Es (fp32)
    #pragma unroll
    for (int nt = 0; nt < 8; nt++) {
        int c = wn + nt * 8 + 2 * tig;
        Es[wm + gid    ][c    ] = acc[nt][0];
        Es[wm + gid    ][c + 1] = acc[nt][1];
        Es[wm + gid + 8][c    ] = acc[nt][2];
        Es[wm + gid + 8][c + 1] = acc[nt][3];
    }
    __syncthreads();
    // RoPE on first 64 dims: pairs (j, j+32), angle = t * 10000^(-j/32)
    for (int it = tid; it < 64 * 32; it += 256) {
        int r = it >> 5, j = it & 31;
        float t = (float)(t0 + r);
        float freq = powf(10000.0f, -(float)j * (1.0f / 32.0f));
        float sn, cs;
        sincosf(t * freq, &sn, &cs);
        float x1 = Es[r][j], x2 = Es[r][j + 32];
        Es[r][j]      = x1 * cs - x2 * sn;
        Es[r][j + 32] = x1 * sn + x2 * cs;
    }
    // Hadamard over 128 (7 butterfly stages in smem)
    for (int step = 1; step < 128; step <<= 1) {
        __syncthreads();
        for (int it = tid; it < 64 * 64; it += 256) {
            int r = it >> 6, p = it & 63;
            int i = ((p & ~(step - 1)) << 1) | (p & (step - 1));
            float a = Es[r][i], b = Es[r][i + step];
            Es[r][i]        = a + b;
            Es[r][i + step] = a - b;
        }
    }
    __syncthreads();
    for (int it = tid; it < 64 * 128; it += 256) {
        int r = it >> 7, d = it & 127;
        g_qprime[((size_t)(t0 + r) * H + h) * D + d] = __float2bfloat16(Es[r][d] * HAD_SCALE);
    }
}

// ---------------------------------------------------------------------------
// Kernel 2: k = rope+hadamard(LN(x @ Wk)). grid 64, 256 threads. BM=64, BN=128.
// ---------------------------------------------------------------------------
__global__ __launch_bounds__(256) void kproj_kernel(const float* __restrict__ x,
                                                    const float* __restrict__ Wk,
                                                    const float* __restrict__ ln_g,
                                                    const float* __restrict__ ln_b) {
    const int t0 = blockIdx.x * 64;
    __shared__ __nv_bfloat16 As[64][40];
    __shared__ __nv_bfloat16 Bs[128][40];
    __shared__ float Es[64][129];
    __shared__ float s_mu[64], s_rs[64];
    const int tid  = threadIdx.x;
    const int lane = tid & 31, warp = tid >> 5;
    const int wm = (warp & 3) * 16;
    const int wn = (warp >> 2) * 64;
    const int gid = lane >> 2, tig = lane & 3;

    float acc[8][4];
    #pragma unroll
    for (int i = 0; i < 8; i++)
        #pragma unroll
        for (int j = 0; j < 4; j++) acc[i][j] = 0.f;

    for (int k0 = 0; k0 < D_MODEL; k0 += 32) {
        #pragma unroll
        for (int i = 0; i < 8; i++) {
            int idx = tid + i * 256;
            int r = idx >> 5, c = idx & 31;
            As[r][c] = __float2bfloat16(x[(size_t)(t0 + r) * D_MODEL + k0 + c]);
        }
        #pragma unroll
        for (int i = 0; i < 16; i++) {
            int idx = tid + i * 256;
            int kk = idx >> 7, n = idx & 127;
            Bs[n][kk] = __float2bfloat16(Wk[(size_t)(k0 + kk) * D + n]);
        }
        __syncthreads();
        #pragma unroll
        for (int kc = 0; kc < 32; kc += 16) {
            uint32_t a[4];
            a[0] = *(const uint32_t*)&As[wm + gid    ][kc + 2 * tig];
            a[1] = *(const uint32_t*)&As[wm + gid + 8][kc + 2 * tig];
            a[2] = *(const uint32_t*)&As[wm + gid    ][kc + 2 * tig + 8];
            a[3] = *(const uint32_t*)&As[wm + gid + 8][kc + 2 * tig + 8];
            #pragma unroll
            for (int nt = 0; nt < 8; nt++) {
                uint32_t b[2];
                b[0] = *(const uint32_t*)&Bs[wn + nt * 8 + gid][kc + 2 * tig];
                b[1] = *(const uint32_t*)&Bs[wn + nt * 8 + gid][kc + 2 * tig + 8];
                mma16816(acc[nt], a, b);
            }
        }
        __syncthreads();
    }
    #pragma unroll
    for (int nt = 0; nt < 8; nt++) {
        int c = wn + nt * 8 + 2 * tig;
        Es[wm + gid    ][c    ] = acc[nt][0];
        Es[wm + gid    ][c + 1] = acc[nt][1];
        Es[wm + gid + 8][c    ] = acc[nt][2];
        Es[wm + gid + 8][c + 1] = acc[nt][3];
    }
    __syncthreads();
    // LayerNorm over D=128 per row
    if (tid < 64) {
        float sum = 0.f, sq = 0.f;
        #pragma unroll 4
        for (int d = 0; d < 128; d++) {
            float v = Es[tid][d];
            sum += v; sq += v * v;
        }
        float mu = sum * (1.0f / 128.0f);
        float var = sq * (1.0f / 128.0f) - mu * mu;
        s_mu[tid] = mu;
        s_rs[tid] = rsqrtf(var + 1e-5f);
    }
    __syncthreads();
    for (int it = tid; it < 64 * 128; it += 256) {
        int r = it >> 7, d = it & 127;
        Es[r][d] = (Es[r][d] - s_mu[r]) * s_rs[r] * ln_g[d] + ln_b[d];
    }
    __syncthreads();
    // RoPE
    for (int it = tid; it < 64 * 32; it += 256) {
        int r = it >> 5, j = it & 31;
        float t = (float)(t0 + r);
        float freq = powf(10000.0f, -(float)j * (1.0f / 32.0f));
        float sn, cs;
        sincosf(t * freq, &sn, &cs);
        float x1 = Es[r][j], x2 = Es[r][j + 32];
        Es[r][j]      = x1 * cs - x2 * sn;
        Es[r][j + 32] = x1 * sn + x2 * cs;
    }
    // Hadamard
    for (int step = 1; step < 128; step <<= 1) {
        __syncthreads();
        for (int it = tid; it < 64 * 64; it += 256) {
            int r = it >> 6, p = it & 63;
            int i = ((p & ~(step - 1)) << 1) | (p & (step - 1));
            float a = Es[r][i], b = Es[r][i + step];
            Es[r][i]        = a + b;
            Es[r][i + step] = a - b;
        }
    }
    __syncthreads();
    for (int it = tid; it < 64 * 128; it += 256) {
        int r = it >> 7, d = it & 127;
        g_kprime[(size_t)(t0 + r) * D + d] = __float2bfloat16(Es[r][d] * HAD_SCALE);
    }
}

// ---------------------------------------------------------------------------
// Kernel 3: w[t][h] = x[t] . Wwt[:,h].  grid 4096, 256 threads (warp per head).
// ---------------------------------------------------------------------------
__global__ __launch_bounds__(256) void w_kernel(const float* __restrict__ x,
                                                const float* __restrict__ Wwt) {
    const int t = blockIdx.x;
    const int warp = threadIdx.x >> 5, lane = threadIdx.x & 31;
    float sum = 0.f;
    for (int k = lane; k < D_MODEL; k += 32)
        sum += x[(size_t)t * D_MODEL + k] * Wwt[(size_t)k * H + warp];
    #pragma unroll
    for (int o = 16; o > 0; o >>= 1) sum += __shfl_xor_sync(0xffffffffu, sum, o);
    if (lane == 0) g_w[(size_t)t * H + warp] = sum;
}

// ---------------------------------------------------------------------------
// Kernel 4: scores. 64x64 tile per CTA, grid (s_tiles=64, t_tiles=64).
// Per head: QK^T (bf16 mma) -> relu -> * w[t,h] accumulate -> masked write.
// ---------------------------------------------------------------------------
__global__ __launch_bounds__(256) void scores_kernel(float* __restrict__ out) {
    const int s0 = blockIdx.x * 64;
    const int t0 = blockIdx.y * 64;
    const int tid = threadIdx.x;

    if (s0 > t0 + 63) {  // fully masked tile
        const float4 neg4 = make_float4(NEG, NEG, NEG, NEG);
        for (int it = tid; it < 64 * 16; it += 256) {
            int r = it >> 4, c = (it & 15) * 4;
            *(float4*)&out[(size_t)(t0 + r) * S_LEN + s0 + c] = neg4;
        }
        return;
    }

    __shared__ __nv_bfloat16 Ks[64][136];   // 272B row stride -> 4-bank/row shift, conflict-free
    __shared__ __nv_bfloat16 Qs[64][136];
    __shared__ float ws[64][8];

    const int lane = tid & 31, warp = tid >> 5;
    const int wm = (warp & 3) * 16;          // 4 m-warps
    const int wn = (warp >> 2) * 32;         // 2 n-warps, 32 cols each
    const int gid = lane >> 2, tig = lane & 3;

    for (int it = tid; it < 64 * 16; it += 256) {         // K tile: 64x128 bf16
        int r = it >> 4, c = (it & 15) * 8;
        *(uint4*)&Ks[r][c] = *(const uint4*)&g_kprime[(size_t)(s0 + r) * D + c];
    }
    for (int it = tid; it < 64 * 8; it += 256)
        ws[it >> 3][it & 7] = g_w[(size_t)(t0 + (it >> 3)) * H + (it & 7)];

    float score[4][4];
    #pragma unroll
    for (int i = 0; i < 4; i++)
        #pragma unroll
        for (int j = 0; j < 4; j++) score[i][j] = 0.f;

    for (int h = 0; h < H; h++) {
        __syncthreads();   // protect Qs (and, first iter, order Ks/ws stores)
        for (int it = tid; it < 64 * 16; it += 256) {
            int r = it >> 4, c = (it & 15) * 8;
            *(uint4*)&Qs[r][c] = *(const uint4*)&g_qprime[((size_t)(t0 + r) * H + h) * D + c];
        }
        __syncthreads();

        float acc[4][4];
        #pragma unroll
        for (int i = 0; i < 4; i++)
            #pragma unroll
            for (int j = 0; j < 4; j++) acc[i][j] = 0.f;

        #pragma unroll
        for (int kc = 0; kc < 128; kc += 16) {
            uint32_t a[4];
            a[0] = *(const uint32_t*)&Qs[wm + gid    ][kc + 2 * tig];
            a[1] = *(const uint32_t*)&Qs[wm + gid + 8][kc + 2 * tig];
            a[2] = *(const uint32_t*)&Qs[wm + gid    ][kc + 2 * tig + 8];
            a[3] = *(const uint32_t*)&Qs[wm + gid + 8][kc + 2 * tig + 8];
            #pragma unroll
            for (int nt = 0; nt < 4; nt++) {
                uint32_t b[2];
                b[0] = *(const uint32_t*)&Ks[wn + nt * 8 + gid][kc + 2 * tig];
                b[1] = *(const uint32_t*)&Ks[wn + nt * 8 + gid][kc + 2 * tig + 8];
                mma16816(acc[nt], a, b);
            }
        }
        float w0 = ws[wm + gid    ][h];
        float w1 = ws[wm + gid + 8][h];
        #pragma unroll
        for (int nt = 0; nt < 4; nt++) {
            score[nt][0] += w0 * fmaxf(acc[nt][0], 0.f);
            score[nt][1] += w0 * fmaxf(acc[nt][1], 0.f);
            score[nt][2] += w1 * fmaxf(acc[nt][2], 0.f);
            score[nt][3] += w1 * fmaxf(acc[nt][3], 0.f);
        }
    }

    const int rt0 = t0 + wm + gid;
    const int rt1 = rt0 + 8;
    #pragma unroll
    for (int nt = 0; nt < 4; nt++) {
        int cs = s0 + wn + nt * 8 + 2 * tig;
        out[(size_t)rt0 * S_LEN + cs    ] = (cs     <= rt0) ? score[nt][0] * HAD_SCALE : NEG;
        out[(size_t)rt0 * S_LEN + cs + 1] = (cs + 1 <= rt0) ? score[nt][1] * HAD_SCALE : NEG;
        out[(size_t)rt1 * S_LEN + cs    ] = (cs     <= rt1) ? score[nt][2] * HAD_SCALE : NEG;
        out[(size_t)rt1 * S_LEN + cs + 1] = (cs + 1 <= rt1) ? score[nt][3] * HAD_SCALE : NEG;
    }
}

// ---------------------------------------------------------------------------
extern "C" void kernel_launch(void* const* d_in, const int* in_sizes, int n_in,
                              void* d_out, int out_size) {
    const float* x    = (const float*)d_in[0];
    const float* qlat = (const float*)d_in[1];
    const float* Wq   = (const float*)d_in[2];
    const float* Wk   = (const float*)d_in[3];
    const float* ln_g = (const float*)d_in[4];
    const float* ln_b = (const float*)d_in[5];
    const float* Wwt  = (const float*)d_in[6];
    float* out = (float*)d_out;

    qproj_kernel<<<dim3(H, S_LEN / 64), 256>>>(qlat, Wq);
    kproj_kernel<<<S_LEN / 64, 256>>>(x, Wk, ln_g, ln_b);
    w_kernel<<<S_LEN, 256>>>(x, Wwt);
    scores_kernel<<<dim3(S_LEN / 64, S_LEN / 64), 256>>>(out);
}

// round 2
// speedup vs baseline: 2.1351x; 2.1351x over previous
#include <cuda_runtime.h>
#include <cuda_bf16.h>
#include <stdint.h>

#define S_LEN 4096
#define D_MODEL 2048
#define D_CQ 1536
#define H 8
#define D 128
#define NEG (-1000000000.0f)
#define HAD_SCALE 0.08838834764831845f   // 128^-0.5

// ---------------- scratch (device globals; no allocation allowed) ----------
__device__ __nv_bfloat16 g_qprime[S_LEN * H * D];     // [t][h][d]
__device__ __nv_bfloat16 g_kprime[S_LEN * D];         // [s][d]
__device__ float         g_w[S_LEN * H];              // [t][h]
__device__ __nv_bfloat16 g_xb [S_LEN * D_MODEL];
__device__ __nv_bfloat16 g_qlb[S_LEN * D_CQ];
__device__ __nv_bfloat16 g_wqb[D_CQ * H * D];
__device__ __nv_bfloat16 g_wkb[D_MODEL * D];

// ---------------- asm helpers ---------------------------------------------
__device__ __forceinline__ uint32_t smem_u32(const void* p) {
    return (uint32_t)__cvta_generic_to_shared(p);
}
__device__ __forceinline__ void cp16(uint32_t dst, const void* src) {
    asm volatile("cp.async.cg.shared.global [%0], [%1], 16;\n" :: "r"(dst), "l"(src));
}
__device__ __forceinline__ void cp_commit() {
    asm volatile("cp.async.commit_group;\n" ::: "memory");
}
template<int N> __device__ __forceinline__ void cp_wait() {
    asm volatile("cp.async.wait_group %0;\n" :: "n"(N) : "memory");
}
__device__ __forceinline__ void ldmx4(uint32_t* r, uint32_t a) {
    asm volatile("ldmatrix.sync.aligned.m8n8.x4.shared.b16 {%0,%1,%2,%3}, [%4];\n"
                 : "=r"(r[0]), "=r"(r[1]), "=r"(r[2]), "=r"(r[3]) : "r"(a));
}
__device__ __forceinline__ void ldmx4t(uint32_t* r, uint32_t a) {
    asm volatile("ldmatrix.sync.aligned.m8n8.x4.trans.shared.b16 {%0,%1,%2,%3}, [%4];\n"
                 : "=r"(r[0]), "=r"(r[1]), "=r"(r[2]), "=r"(r[3]) : "r"(a));
}
__device__ __forceinline__ void mma16816(float c[4], const uint32_t a[4], const uint32_t b[2]) {
    asm volatile(
        "mma.sync.aligned.m16n8k16.row.col.f32.bf16.bf16.f32 "
        "{%0,%1,%2,%3}, {%4,%5,%6,%7}, {%8,%9}, {%0,%1,%2,%3};\n"
        : "+f"(c[0]), "+f"(c[1]), "+f"(c[2]), "+f"(c[3])
        : "r"(a[0]), "r"(a[1]), "r"(a[2]), "r"(a[3]), "r"(b[0]), "r"(b[1]));
}

// ---------------- fp32 -> bf16 convert ------------------------------------
__global__ __launch_bounds__(256) void cvt_kernel(const float* __restrict__ s,
                                                  __nv_bfloat16* __restrict__ d, int n) {
    int i = (blockIdx.x * 256 + threadIdx.x) * 4;
    if (i >= n) return;
    float4 v = *(const float4*)(s + i);
    __nv_bfloat162 p0 = __floats2bfloat162_rn(v.x, v.y);
    __nv_bfloat162 p1 = __floats2bfloat162_rn(v.z, v.w);
    uint2 u;
    u.x = *(uint32_t*)&p0;
    u.y = *(uint32_t*)&p1;
    *(uint2*)(d + i) = u;
}

// ---------------------------------------------------------------------------
// Projection GEMM: C[128x128] = A[128xK] @ B[Kx128(+n0)] in bf16, fused
// epilogue (optional LN, then RoPE, then Hadamard), writes bf16.
// grid (Ntot/128, 4096/128), 256 threads. 3-stage cp.async pipeline, BK=32.
// dyn smem: 3*(128*80 + 32*272) = 56832 B; Es (64x132 f32) aliases it.
// ---------------------------------------------------------------------------
template<bool LN>
__global__ __launch_bounds__(256, 2) void proj_kernel(
    const __nv_bfloat16* __restrict__ A, const __nv_bfloat16* __restrict__ B,
    int Kdim, int Ntot,
    const float* __restrict__ ln_g, const float* __restrict__ ln_b,
    __nv_bfloat16* __restrict__ outp)
{
    extern __shared__ char sm[];
    const int n0 = blockIdx.x * 128;
    const int m0 = blockIdx.y * 128;
    const int tid = threadIdx.x, lane = tid & 31, warp = tid >> 5;
    const int wm = (warp & 3) * 32;     // 4 m-warps, 32 rows each
    const int wn = (warp >> 2) * 64;    // 2 n-warps, 64 cols each
    const int gid = lane >> 2, tig = lane & 3;

    __shared__ float s_mu[64], s_rs[64];

    float acc[2][8][4];
    #pragma unroll
    for (int mt = 0; mt < 2; mt++)
        #pragma unroll
        for (int nt = 0; nt < 8; nt++)
            #pragma unroll
            for (int j = 0; j < 4; j++) acc[mt][nt][j] = 0.f;

    const int KT = Kdim >> 5;

    auto issue = [&](int st, int k0) {
        char* as = sm + st * 10240;
        char* bs = sm + 30720 + st * 8704;
        #pragma unroll
        for (int i = 0; i < 2; i++) {
            int c = tid + i * 256;
            int r = c >> 2, sg = c & 3;
            cp16(smem_u32(as + r * 80 + sg * 16),
                 A + (size_t)(m0 + r) * Kdim + k0 + sg * 8);
        }
        #pragma unroll
        for (int i = 0; i < 2; i++) {
            int c = tid + i * 256;
            int r = c >> 4, sg = c & 15;
            cp16(smem_u32(bs + r * 272 + sg * 16),
                 B + (size_t)(k0 + r) * Ntot + n0 + sg * 8);
        }
    };

    issue(0, 0);  cp_commit();
    issue(1, 32); cp_commit();

    for (int kt = 0; kt < KT; kt++) {
        cp_wait<1>();
        __syncthreads();
        if (kt + 2 < KT) issue((kt + 2) % 3, (kt + 2) * 32);
        cp_commit();
        const char* as = sm + (kt % 3) * 10240;
        const char* bs = sm + 30720 + (kt % 3) * 8704;
        #pragma unroll
        for (int kc = 0; kc < 32; kc += 16) {
            uint32_t af[2][4];
            #pragma unroll
            for (int mt = 0; mt < 2; mt++) {
                uint32_t ad = smem_u32(as + (wm + mt * 16 + (lane & 15)) * 80
                                          + (kc + 8 * (lane >> 4)) * 2);
                ldmx4(af[mt], ad);
            }
            #pragma unroll
            for (int ng = 0; ng < 4; ng++) {
                uint32_t bf[4];
                int row  = kc + ((lane >> 3) & 1) * 8 + (lane & 7);
                int ncol = wn + ng * 16 + 8 * (lane >> 4);
                ldmx4t(bf, smem_u32(bs + row * 272 + ncol * 2));
                #pragma unroll
                for (int mt = 0; mt < 2; mt++) {
                    mma16816(acc[mt][2 * ng],     af[mt], bf + 0);
                    mma16816(acc[mt][2 * ng + 1], af[mt], bf + 2);
                }
            }
        }
    }
    __syncthreads();

    // epilogue in two 64-row passes; Es aliases the stage buffers
    float* Es = (float*)sm;   // [64][132]
    for (int p = 0; p < 2; p++) {
        if (((warp & 3) >> 1) == p) {
            int er = wm - p * 64;
            #pragma unroll
            for (int mt = 0; mt < 2; mt++)
                #pragma unroll
                for (int nt = 0; nt < 8; nt++) {
                    int r = er + mt * 16 + gid;
                    int c = wn + nt * 8 + 2 * tig;
                    Es[r * 132 + c]           = acc[mt][nt][0];
                    Es[r * 132 + c + 1]       = acc[mt][nt][1];
                    Es[(r + 8) * 132 + c]     = acc[mt][nt][2];
                    Es[(r + 8) * 132 + c + 1] = acc[mt][nt][3];
                }
        }
        __syncthreads();
        if (LN) {
            if (tid < 64) {
                float sum = 0.f, sq = 0.f;
                #pragma unroll 4
                for (int d2 = 0; d2 < 128; d2++) {
                    float v = Es[tid * 132 + d2];
                    sum += v; sq += v * v;
                }
                float mu  = sum * (1.0f / 128.0f);
                float var = sq * (1.0f / 128.0f) - mu * mu;
                s_mu[tid] = mu;
                s_rs[tid] = rsqrtf(var + 1e-5f);
            }
            __syncthreads();
            for (int it = tid; it < 64 * 128; it += 256) {
                int r = it >> 7, d2 = it & 127;
                Es[r * 132 + d2] = (Es[r * 132 + d2] - s_mu[r]) * s_rs[r] * ln_g[d2] + ln_b[d2];
            }
            __syncthreads();
        }
        // RoPE: pairs (j, j+32), j<32
        for (int it = tid; it < 64 * 32; it += 256) {
            int r = it >> 5, j = it & 31;
            float t = (float)(m0 + p * 64 + r);
            float freq = powf(10000.0f, -(float)j * (1.0f / 32.0f));
            float sn, cs;
            sincosf(t * freq, &sn, &cs);
            float x1 = Es[r * 132 + j], x2 = Es[r * 132 + j + 32];
            Es[r * 132 + j]      = x1 * cs - x2 * sn;
            Es[r * 132 + j + 32] = x1 * sn + x2 * cs;
        }
        // Hadamard (7 butterfly stages)
        for (int step = 1; step < 128; step <<= 1) {
            __syncthreads();
            for (int it = tid; it < 64 * 64; it += 256) {
                int r = it >> 6, pp = it & 63;
                int i = ((pp & ~(step - 1)) << 1) | (pp & (step - 1));
                float a = Es[r * 132 + i], b = Es[r * 132 + i + step];
                Es[r * 132 + i]        = a + b;
                Es[r * 132 + i + step] = a - b;
            }
        }
        __syncthreads();
        for (int it = tid; it < 64 * 128; it += 256) {
            int r = it >> 7, d2 = it & 127;
            int t = m0 + p * 64 + r;
            outp[(size_t)t * Ntot + n0 + d2] = __float2bfloat16(Es[r * 132 + d2] * HAD_SCALE);
        }
        __syncthreads();
    }
}

// ---------------------------------------------------------------------------
// w[t][h] = x[t] . Wwt[:,h]
// ---------------------------------------------------------------------------
__global__ __launch_bounds__(256) void w_kernel(const float* __restrict__ x,
                                                const float* __restrict__ Wwt) {
    const int t = blockIdx.x;
    const int warp = threadIdx.x >> 5, lane = threadIdx.x & 31;
    float sum = 0.f;
    for (int k = lane; k < D_MODEL; k += 32)
        sum += x[(size_t)t * D_MODEL + k] * Wwt[(size_t)k * H + warp];
    #pragma unroll
    for (int o = 16; o > 0; o >>= 1) sum += __shfl_xor_sync(0xffffffffu, sum, o);
    if (lane == 0) g_w[(size_t)t * H + warp] = sum;
}

// ---------------------------------------------------------------------------
// scores: tile 64(t) x 128(s) per CTA, grid (32, 64). K-tile resident in
// smem; per-head Q double-buffered via cp.async. ldmatrix fragments.
// dyn smem: Ks 128*272 + Qs 2*64*272 = 69632 B.
// ---------------------------------------------------------------------------
__global__ __launch_bounds__(256, 2) void scores_kernel(float* __restrict__ out) {
    const int s0 = blockIdx.x * 128;
    const int t0 = blockIdx.y * 64;
    const int tid = threadIdx.x;

    if (s0 > t0 + 63) {   // fully masked tile
        const float4 n4 = make_float4(NEG, NEG, NEG, NEG);
        for (int it = tid; it < 64 * 32; it += 256) {
            int r = it >> 5, c = (it & 31) * 4;
            *(float4*)&out[(size_t)(t0 + r) * S_LEN + s0 + c] = n4;
        }
        return;
    }

    extern __shared__ char sm[];
    char* Ks = sm;                          // [128][136] bf16
    __shared__ float ws[64][8];

    const int lane = tid & 31, warp = tid >> 5;
    const int wm = (warp & 1) * 32;         // 2 m-warps
    const int wn = (warp >> 1) * 32;        // 4 n-warps
    const int gid = lane >> 2, tig = lane & 3;

    for (int it = tid; it < 512; it += 256)
        ws[it >> 3][it & 7] = g_w[(size_t)(t0 + (it >> 3)) * H + (it & 7)];

    #pragma unroll
    for (int i = 0; i < 8; i++) {           // K tile 128x128 bf16
        int c = tid + i * 256;
        int r = c >> 4, sg = c & 15;
        cp16(smem_u32(Ks + r * 272 + sg * 16), g_kprime + (size_t)(s0 + r) * D + sg * 8);
    }
    {
        char* Q0 = sm + 34816;
        #pragma unroll
        for (int i = 0; i < 4; i++) {       // Q head 0: 64x128
            int c = tid + i * 256;
            int r = c >> 4, sg = c & 15;
            cp16(smem_u32(Q0 + r * 272 + sg * 16),
                 g_qprime + ((size_t)(t0 + r) * H + 0) * D + sg * 8);
        }
    }
    cp_commit();

    float score[2][4][4];
    #pragma unroll
    for (int mt = 0; mt < 2; mt++)
        #pragma unroll
        for (int nt = 0; nt < 4; nt++)
            #pragma unroll
            for (int j = 0; j < 4; j++) score[mt][nt][j] = 0.f;

    for (int h = 0; h < H; h++) {
        cp_wait<0>();
        __syncthreads();
        if (h < 7) {
            char* Qn = sm + 34816 + ((h + 1) & 1) * 17408;
            #pragma unroll
            for (int i = 0; i < 4; i++) {
                int c = tid + i * 256;
                int r = c >> 4, sg = c & 15;
                cp16(smem_u32(Qn + r * 272 + sg * 16),
                     g_qprime + ((size_t)(t0 + r) * H + h + 1) * D + sg * 8);
            }
            cp_commit();
        }
        const char* Qb = sm + 34816 + (h & 1) * 17408;

        float acc[2][4][4];
        #pragma unroll
        for (int mt = 0; mt < 2; mt++)
            #pragma unroll
            for (int nt = 0; nt < 4; nt++)
                #pragma unroll
                for (int j = 0; j < 4; j++) acc[mt][nt][j] = 0.f;

        #pragma unroll
        for (int kc = 0; kc < 128; kc += 16) {
            uint32_t af[2][4];
            #pragma unroll
            for (int mt = 0; mt < 2; mt++) {
                uint32_t ad = smem_u32(Qb + (wm + mt * 16 + (lane & 15)) * 272
                                          + (kc + 8 * (lane >> 4)) * 2);
                ldmx4(af[mt], ad);
            }
            #pragma unroll
            for (int ng = 0; ng < 2; ng++) {
                uint32_t bf[4];
                int row = wn + ng * 16 + ((lane >> 4) << 3) + (lane & 7);
                int ck  = kc + 8 * ((lane >> 3) & 1);
                ldmx4(bf, smem_u32(Ks + row * 272 + ck * 2));
                #pragma unroll
                for (int mt = 0; mt < 2; mt++) {
                    mma16816(acc[mt][2 * ng],     af[mt], bf + 0);
                    mma16816(acc[mt][2 * ng + 1], af[mt], bf + 2);
                }
            }
        }
        #pragma unroll
        for (int mt = 0; mt < 2; mt++) {
            float w0 = ws[wm + mt * 16 + gid][h];
            float w1 = ws[wm + mt * 16 + 8 + gid][h];
            #pragma unroll
            for (int nt = 0; nt < 4; nt++) {
                score[mt][nt][0] += w0 * fmaxf(acc[mt][nt][0], 0.f);
                score[mt][nt][1] += w0 * fmaxf(acc[mt][nt][1], 0.f);
                score[mt][nt][2] += w1 * fmaxf(acc[mt][nt][2], 0.f);
                score[mt][nt][3] += w1 * fmaxf(acc[mt][nt][3], 0.f);
            }
        }
    }

    #pragma unroll
    for (int mt = 0; mt < 2; mt++) {
        int r0 = t0 + wm + mt * 16 + gid;
        int r1 = r0 + 8;
        #pragma unroll
        for (int nt = 0; nt < 4; nt++) {
            int cs = s0 + wn + nt * 8 + 2 * tig;
            out[(size_t)r0 * S_LEN + cs    ] = (cs     <= r0) ? score[mt][nt][0] * HAD_SCALE : NEG;
            out[(size_t)r0 * S_LEN + cs + 1] = (cs + 1 <= r0) ? score[mt][nt][1] * HAD_SCALE : NEG;
            out[(size_t)r1 * S_LEN + cs    ] = (cs     <= r1) ? score[mt][nt][2] * HAD_SCALE : NEG;
            out[(size_t)r1 * S_LEN + cs + 1] = (cs + 1 <= r1) ? score[mt][nt][3] * HAD_SCALE : NEG;
        }
    }
}

// ---------------------------------------------------------------------------
extern "C" void kernel_launch(void* const* d_in, const int* in_sizes, int n_in,
                              void* d_out, int out_size) {
    const float* x    = (const float*)d_in[0];
    const float* qlat = (const float*)d_in[1];
    const float* Wq   = (const float*)d_in[2];
    const float* Wk   = (const float*)d_in[3];
    const float* ln_g = (const float*)d_in[4];
    const float* ln_b = (const float*)d_in[5];
    const float* Wwt  = (const float*)d_in[6];
    float* out = (float*)d_out;

    void *xb, *qlb, *wqb, *wkb, *qp, *kp;
    cudaGetSymbolAddress(&xb,  g_xb);
    cudaGetSymbolAddress(&qlb, g_qlb);
    cudaGetSymbolAddress(&wqb, g_wqb);
    cudaGetSymbolAddress(&wkb, g_wkb);
    cudaGetSymbolAddress(&qp,  g_qprime);
    cudaGetSymbolAddress(&kp,  g_kprime);

    cudaFuncSetAttribute(proj_kernel<false>, cudaFuncAttributeMaxDynamicSharedMemorySize, 57344);
    cudaFuncSetAttribute(proj_kernel<true>,  cudaFuncAttributeMaxDynamicSharedMemorySize, 57344);
    cudaFuncSetAttribute(scores_kernel,      cudaFuncAttributeMaxDynamicSharedMemorySize, 71680);

    cvt_kernel<<<(S_LEN * D_MODEL) / 1024, 256>>>(x,    (__nv_bfloat16*)xb,  S_LEN * D_MODEL);
    cvt_kernel<<<(S_LEN * D_CQ)    / 1024, 256>>>(qlat, (__nv_bfloat16*)qlb, S_LEN * D_CQ);
    cvt_kernel<<<(D_CQ * H * D)    / 1024, 256>>>(Wq,   (__nv_bfloat16*)wqb, D_CQ * H * D);
    cvt_kernel<<<(D_MODEL * D)     / 1024, 256>>>(Wk,   (__nv_bfloat16*)wkb, D_MODEL * D);

    proj_kernel<false><<<dim3(H, S_LEN / 128), 256, 57344>>>(
        (const __nv_bfloat16*)qlb, (const __nv_bfloat16*)wqb,
        D_CQ, H * D, nullptr, nullptr, (__nv_bfloat16*)qp);
    proj_kernel<true><<<dim3(1, S_LEN / 128), 256, 57344>>>(
        (const __nv_bfloat16*)xb, (const __nv_bfloat16*)wkb,
        D_MODEL, D, ln_g, ln_b, (__nv_bfloat16*)kp);
    w_kernel<<<S_LEN, 256>>>(x, Wwt);
    scores_kernel<<<dim3(S_LEN / 128, S_LEN / 64), 256, 71680>>>(out);
}

// round 3
// speedup vs baseline: 2.4782x; 1.1607x over previous
#include <cuda_runtime.h>
#include <cuda_bf16.h>
#include <stdint.h>

#define S_LEN 4096
#define D_MODEL 2048
#define D_CQ 1536
#define H 8
#define D 128
#define NEG (-1000000000.0f)
#define HAD_SCALE 0.08838834764831845f   // 128^-0.5

// ---------------- scratch (device globals; no allocation allowed) ----------
__device__ __nv_bfloat16 g_qprime[S_LEN * H * D];     // [t][h][d]
__device__ __nv_bfloat16 g_kprime[S_LEN * D];         // [s][d]
__device__ float         g_w[S_LEN * H];              // [t][h]
__device__ __nv_bfloat16 g_xb [S_LEN * D_MODEL];
__device__ __nv_bfloat16 g_qlb[S_LEN * D_CQ];
__device__ __nv_bfloat16 g_wqb[D_CQ * H * D];
__device__ __nv_bfloat16 g_wkb[D_MODEL * D];

// ---------------- asm helpers ---------------------------------------------
__device__ __forceinline__ uint32_t smem_u32(const void* p) {
    return (uint32_t)__cvta_generic_to_shared(p);
}
__device__ __forceinline__ void cp16(uint32_t dst, const void* src) {
    asm volatile("cp.async.cg.shared.global [%0], [%1], 16;\n" :: "r"(dst), "l"(src));
}
__device__ __forceinline__ void cp_commit() {
    asm volatile("cp.async.commit_group;\n" ::: "memory");
}
template<int N> __device__ __forceinline__ void cp_wait() {
    asm volatile("cp.async.wait_group %0;\n" :: "n"(N) : "memory");
}
__device__ __forceinline__ void ldmx4(uint32_t* r, uint32_t a) {
    asm volatile("ldmatrix.sync.aligned.m8n8.x4.shared.b16 {%0,%1,%2,%3}, [%4];\n"
                 : "=r"(r[0]), "=r"(r[1]), "=r"(r[2]), "=r"(r[3]) : "r"(a));
}
__device__ __forceinline__ void ldmx4t(uint32_t* r, uint32_t a) {
    asm volatile("ldmatrix.sync.aligned.m8n8.x4.trans.shared.b16 {%0,%1,%2,%3}, [%4];\n"
                 : "=r"(r[0]), "=r"(r[1]), "=r"(r[2]), "=r"(r[3]) : "r"(a));
}
__device__ __forceinline__ void mma16816(float c[4], const uint32_t a[4], const uint32_t b[2]) {
    asm volatile(
        "mma.sync.aligned.m16n8k16.row.col.f32.bf16.bf16.f32 "
        "{%0,%1,%2,%3}, {%4,%5,%6,%7}, {%8,%9}, {%0,%1,%2,%3};\n"
        : "+f"(c[0]), "+f"(c[1]), "+f"(c[2]), "+f"(c[3])
        : "r"(a[0]), "r"(a[1]), "r"(a[2]), "r"(a[3]), "r"(b[0]), "r"(b[1]));
}

// ---------------- fp32 -> bf16 convert (all 4 arrays in one launch) --------
#define N_X  (S_LEN * D_MODEL)            // 8388608
#define N_QL (S_LEN * D_CQ)               // 6291456
#define N_WQ (D_CQ * H * D)               // 1572864
#define N_WK (D_MODEL * D)                // 262144
#define CVT_BLOCKS ((N_X + N_QL + N_WQ + N_WK) / 1024)

__global__ __launch_bounds__(256) void cvt_all_kernel(const float* __restrict__ x,
                                                      const float* __restrict__ ql,
                                                      const float* __restrict__ wq,
                                                      const float* __restrict__ wk) {
    long i = (long)(blockIdx.x * 256 + threadIdx.x) * 4;
    const float* s;
    __nv_bfloat16* d;
    long base;
    const long c0 = N_X, c1 = c0 + N_QL, c2 = c1 + N_WQ;
    if (i < c0)      { s = x;  d = g_xb;  base = 0;  }
    else if (i < c1) { s = ql; d = g_qlb; base = c0; }
    else if (i < c2) { s = wq; d = g_wqb; base = c1; }
    else             { s = wk; d = g_wkb; base = c2; }
    long j = i - base;
    float4 v = *(const float4*)(s + j);
    __nv_bfloat162 p0 = __floats2bfloat162_rn(v.x, v.y);
    __nv_bfloat162 p1 = __floats2bfloat162_rn(v.z, v.w);
    uint2 u;
    u.x = *(uint32_t*)&p0;
    u.y = *(uint32_t*)&p1;
    *(uint2*)(d + j) = u;
}

// ---------------------------------------------------------------------------
// Merged projection GEMM: grid (9, 32). blockIdx.x 0..7 -> Q head tiles,
// 8 -> K tile (with LayerNorm). 128x128 C tile, BK=32, 3-stage cp.async.
// Fused epilogue: (LN) -> RoPE -> Hadamard -> bf16 out.
// dyn smem: 3*(128*80 + 32*272) = 56832 B; Es (64x132 f32) aliases it.
// ---------------------------------------------------------------------------
__global__ __launch_bounds__(256, 2) void proj_kernel(
    const __nv_bfloat16* __restrict__ Aq, const __nv_bfloat16* __restrict__ Bq,
    const __nv_bfloat16* __restrict__ Ak, const __nv_bfloat16* __restrict__ Bk,
    const float* __restrict__ ln_g, const float* __restrict__ ln_b)
{
    extern __shared__ char sm[];
    const int tile = blockIdx.x;
    const bool isK = (tile == 8);
    const __nv_bfloat16* A = isK ? Ak : Aq;
    const __nv_bfloat16* B = isK ? Bk : Bq;
    const int Kdim = isK ? D_MODEL : D_CQ;
    const int Bld  = isK ? D : (H * D);
    const int n0   = isK ? 0 : tile * 128;
    __nv_bfloat16* outp = isK ? g_kprime : g_qprime;
    const int Old  = isK ? D : (H * D);

    const int m0 = blockIdx.y * 128;
    const int tid = threadIdx.x, lane = tid & 31, warp = tid >> 5;
    const int wm = (warp & 3) * 32;     // 4 m-warps, 32 rows each
    const int wn = (warp >> 2) * 64;    // 2 n-warps, 64 cols each
    const int gid = lane >> 2, tig = lane & 3;

    __shared__ float s_mu[64], s_rs[64];

    float acc[2][8][4];
    #pragma unroll
    for (int mt = 0; mt < 2; mt++)
        #pragma unroll
        for (int nt = 0; nt < 8; nt++)
            #pragma unroll
            for (int j = 0; j < 4; j++) acc[mt][nt][j] = 0.f;

    const int KT = Kdim >> 5;

    auto issue = [&](int st, int k0) {
        char* as = sm + st * 10240;
        char* bs = sm + 30720 + st * 8704;
        #pragma unroll
        for (int i = 0; i < 2; i++) {
            int c = tid + i * 256;
            int r = c >> 2, sg = c & 3;
            cp16(smem_u32(as + r * 80 + sg * 16),
                 A + (size_t)(m0 + r) * Kdim + k0 + sg * 8);
        }
        #pragma unroll
        for (int i = 0; i < 2; i++) {
            int c = tid + i * 256;
            int r = c >> 4, sg = c & 15;
            cp16(smem_u32(bs + r * 272 + sg * 16),
                 B + (size_t)(k0 + r) * Bld + n0 + sg * 8);
        }
    };

    issue(0, 0);  cp_commit();
    issue(1, 32); cp_commit();

    for (int kt = 0; kt < KT; kt++) {
        cp_wait<1>();
        __syncthreads();
        if (kt + 2 < KT) issue((kt + 2) % 3, (kt + 2) * 32);
        cp_commit();
        const char* as = sm + (kt % 3) * 10240;
        const char* bs = sm + 30720 + (kt % 3) * 8704;
        #pragma unroll
        for (int kc = 0; kc < 32; kc += 16) {
            uint32_t af[2][4];
            #pragma unroll
            for (int mt = 0; mt < 2; mt++) {
                uint32_t ad = smem_u32(as + (wm + mt * 16 + (lane & 15)) * 80
                                          + (kc + 8 * (lane >> 4)) * 2);
                ldmx4(af[mt], ad);
            }
            #pragma unroll
            for (int ng = 0; ng < 4; ng++) {
                uint32_t bf[4];
                int row  = kc + ((lane >> 3) & 1) * 8 + (lane & 7);
                int ncol = wn + ng * 16 + 8 * (lane >> 4);
                ldmx4t(bf, smem_u32(bs + row * 272 + ncol * 2));
                #pragma unroll
                for (int mt = 0; mt < 2; mt++) {
                    mma16816(acc[mt][2 * ng],     af[mt], bf + 0);
                    mma16816(acc[mt][2 * ng + 1], af[mt], bf + 2);
                }
            }
        }
    }
    __syncthreads();

    // epilogue in two 64-row passes; Es aliases the stage buffers
    float* Es = (float*)sm;   // [64][132]
    for (int p = 0; p < 2; p++) {
        if (((warp & 3) >> 1) == p) {
            int er = wm - p * 64;
            #pragma unroll
            for (int mt = 0; mt < 2; mt++)
                #pragma unroll
                for (int nt = 0; nt < 8; nt++) {
                    int r = er + mt * 16 + gid;
                    int c = wn + nt * 8 + 2 * tig;
                    Es[r * 132 + c]           = acc[mt][nt][0];
                    Es[r * 132 + c + 1]       = acc[mt][nt][1];
                    Es[(r + 8) * 132 + c]     = acc[mt][nt][2];
                    Es[(r + 8) * 132 + c + 1] = acc[mt][nt][3];
                }
        }
        __syncthreads();
        if (isK) {
            if (tid < 64) {
                float sum = 0.f, sq = 0.f;
                #pragma unroll 4
                for (int d2 = 0; d2 < 128; d2++) {
                    float v = Es[tid * 132 + d2];
                    sum += v; sq += v * v;
                }
                float mu  = sum * (1.0f / 128.0f);
                float var = sq * (1.0f / 128.0f) - mu * mu;
                s_mu[tid] = mu;
                s_rs[tid] = rsqrtf(var + 1e-5f);
            }
            __syncthreads();
            for (int it = tid; it < 64 * 128; it += 256) {
                int r = it >> 7, d2 = it & 127;
                Es[r * 132 + d2] = (Es[r * 132 + d2] - s_mu[r]) * s_rs[r] * ln_g[d2] + ln_b[d2];
            }
            __syncthreads();
        }
        // RoPE: pairs (j, j+32), j<32; freq = 10000^(-j/32) = exp2(-j*log2(1e4)/32)
        for (int it = tid; it < 64 * 32; it += 256) {
            int r = it >> 5, j = it & 31;
            float t = (float)(m0 + p * 64 + r);
            float freq = exp2f((float)j * (-0.41524101186092029f));
            float sn, cs;
            sincosf(t * freq, &sn, &cs);
            float x1 = Es[r * 132 + j], x2 = Es[r * 132 + j + 32];
            Es[r * 132 + j]      = x1 * cs - x2 * sn;
            Es[r * 132 + j + 32] = x1 * sn + x2 * cs;
        }
        // Hadamard (7 butterfly stages)
        for (int step = 1; step < 128; step <<= 1) {
            __syncthreads();
            for (int it = tid; it < 64 * 64; it += 256) {
                int r = it >> 6, pp = it & 63;
                int i = ((pp & ~(step - 1)) << 1) | (pp & (step - 1));
                float a = Es[r * 132 + i], b = Es[r * 132 + i + step];
                Es[r * 132 + i]        = a + b;
                Es[r * 132 + i + step] = a - b;
            }
        }
        __syncthreads();
        for (int it = tid; it < 64 * 128; it += 256) {
            int r = it >> 7, d2 = it & 127;
            int t = m0 + p * 64 + r;
            outp[(size_t)t * Old + n0 + d2] = __float2bfloat16(Es[r * 132 + d2] * HAD_SCALE);
        }
        __syncthreads();
    }
}

// ---------------------------------------------------------------------------
// w[t][h] = x[t] . Wwt[:,h]   (reads bf16 x copy; Wwt fp32)
// ---------------------------------------------------------------------------
__global__ __launch_bounds__(256) void w_kernel(const float* __restrict__ Wwt) {
    const int t = blockIdx.x;
    const int warp = threadIdx.x >> 5, lane = threadIdx.x & 31;
    float sum = 0.f;
    for (int k = lane; k < D_MODEL; k += 32)
        sum += __bfloat162float(g_xb[(size_t)t * D_MODEL + k]) * Wwt[(size_t)k * H + warp];
    #pragma unroll
    for (int o = 16; o > 0; o >>= 1) sum += __shfl_xor_sync(0xffffffffu, sum, o);
    if (lane == 0) g_w[(size_t)t * H + warp] = sum;
}

// ---------------------------------------------------------------------------
// scores: tile 128(t) x 128(s) per CTA, grid (32, 32), 512 threads.
// K-tile resident; per-head Q double-buffered via cp.async.
// dyn smem: Ks 128*272 + Qs 2*128*272 = 104448 B.
// ---------------------------------------------------------------------------
__global__ __launch_bounds__(512) void scores_kernel(float* __restrict__ out) {
    const int s0 = blockIdx.x * 128;
    const int t0 = blockIdx.y * 128;
    const int tid = threadIdx.x;

    if (s0 > t0 + 127) {   // fully masked tile
        const float4 n4 = make_float4(NEG, NEG, NEG, NEG);
        for (int it = tid; it < 128 * 32; it += 512) {
            int r = it >> 5, c = (it & 31) * 4;
            *(float4*)&out[(size_t)(t0 + r) * S_LEN + s0 + c] = n4;
        }
        return;
    }

    extern __shared__ char sm[];
    char* Ks = sm;                          // [128][136] bf16
    __shared__ float ws[128][8];

    const int lane = tid & 31, warp = tid >> 5;
    const int wm = (warp & 3) * 32;         // 4 m-warps, 32 rows
    const int wn = (warp >> 2) * 32;        // 4 n-warps, 32 cols
    const int gid = lane >> 2, tig = lane & 3;

    for (int it = tid; it < 1024; it += 512)
        ws[it >> 3][it & 7] = g_w[(size_t)(t0 + (it >> 3)) * H + (it & 7)];

    #pragma unroll
    for (int i = 0; i < 4; i++) {           // K tile 128x128 bf16
        int c = tid + i * 512;
        int r = c >> 4, sg = c & 15;
        cp16(smem_u32(Ks + r * 272 + sg * 16), g_kprime + (size_t)(s0 + r) * D + sg * 8);
    }
    {
        char* Q0 = sm + 34816;
        #pragma unroll
        for (int i = 0; i < 4; i++) {       // Q head 0: 128x128
            int c = tid + i * 512;
            int r = c >> 4, sg = c & 15;
            cp16(smem_u32(Q0 + r * 272 + sg * 16),
                 g_qprime + ((size_t)(t0 + r) * H + 0) * D + sg * 8);
        }
    }
    cp_commit();

    float score[2][4][4];
    #pragma unroll
    for (int mt = 0; mt < 2; mt++)
        #pragma unroll
        for (int nt = 0; nt < 4; nt++)
            #pragma unroll
            for (int j = 0; j < 4; j++) score[mt][nt][j] = 0.f;

    for (int h = 0; h < H; h++) {
        cp_wait<0>();
        __syncthreads();
        if (h < 7) {
            char* Qn = sm + 34816 + ((h + 1) & 1) * 34816;
            #pragma unroll
            for (int i = 0; i < 4; i++) {
                int c = tid + i * 512;
                int r = c >> 4, sg = c & 15;
                cp16(smem_u32(Qn + r * 272 + sg * 16),
                     g_qprime + ((size_t)(t0 + r) * H + h + 1) * D + sg * 8);
            }
            cp_commit();
        }
        const char* Qb = sm + 34816 + (h & 1) * 34816;

        float acc[2][4][4];
        #pragma unroll
        for (int mt = 0; mt < 2; mt++)
            #pragma unroll
            for (int nt = 0; nt < 4; nt++)
                #pragma unroll
                for (int j = 0; j < 4; j++) acc[mt][nt][j] = 0.f;

        #pragma unroll
        for (int kc = 0; kc < 128; kc += 16) {
            uint32_t af[2][4];
            #pragma unroll
            for (int mt = 0; mt < 2; mt++) {
                uint32_t ad = smem_u32(Qb + (wm + mt * 16 + (lane & 15)) * 272
                                          + (kc + 8 * (lane >> 4)) * 2);
                ldmx4(af[mt], ad);
            }
            #pragma unroll
            for (int ng = 0; ng < 2; ng++) {
                uint32_t bf[4];
                int row = wn + ng * 16 + ((lane >> 4) << 3) + (lane & 7);
                int ck  = kc + 8 * ((lane >> 3) & 1);
                ldmx4(bf, smem_u32(Ks + row * 272 + ck * 2));
                #pragma unroll
                for (int mt = 0; mt < 2; mt++) {
                    mma16816(acc[mt][2 * ng],     af[mt], bf + 0);
                    mma16816(acc[mt][2 * ng + 1], af[mt], bf + 2);
                }
            }
        }
        #pragma unroll
        for (int mt = 0; mt < 2; mt++) {
            float w0 = ws[wm + mt * 16 + gid][h];
            float w1 = ws[wm + mt * 16 + 8 + gid][h];
            #pragma unroll
            for (int nt = 0; nt < 4; nt++) {
                score[mt][nt][0] += w0 * fmaxf(acc[mt][nt][0], 0.f);
                score[mt][nt][1] += w0 * fmaxf(acc[mt][nt][1], 0.f);
                score[mt][nt][2] += w1 * fmaxf(acc[mt][nt][2], 0.f);
                score[mt][nt][3] += w1 * fmaxf(acc[mt][nt][3], 0.f);
            }
        }
    }

    #pragma unroll
    for (int mt = 0; mt < 2; mt++) {
        int r0 = t0 + wm + mt * 16 + gid;
        int r1 = r0 + 8;
        #pragma unroll
        for (int nt = 0; nt < 4; nt++) {
            int cs = s0 + wn + nt * 8 + 2 * tig;
            out[(size_t)r0 * S_LEN + cs    ] = (cs     <= r0) ? score[mt][nt][0] * HAD_SCALE : NEG;
            out[(size_t)r0 * S_LEN + cs + 1] = (cs + 1 <= r0) ? score[mt][nt][1] * HAD_SCALE : NEG;
            out[(size_t)r1 * S_LEN + cs    ] = (cs     <= r1) ? score[mt][nt][2] * HAD_SCALE : NEG;
            out[(size_t)r1 * S_LEN + cs + 1] = (cs + 1 <= r1) ? score[mt][nt][3] * HAD_SCALE : NEG;
        }
    }
}

// ---------------------------------------------------------------------------
extern "C" void kernel_launch(void* const* d_in, const int* in_sizes, int n_in,
                              void* d_out, int out_size) {
    const float* x    = (const float*)d_in[0];
    const float* qlat = (const float*)d_in[1];
    const float* Wq   = (const float*)d_in[2];
    const float* Wk   = (const float*)d_in[3];
    const float* ln_g = (const float*)d_in[4];
    const float* ln_b = (const float*)d_in[5];
    const float* Wwt  = (const float*)d_in[6];
    float* out = (float*)d_out;

    void *xb, *qlb, *wqb, *wkb;
    cudaGetSymbolAddress(&xb,  g_xb);
    cudaGetSymbolAddress(&qlb, g_qlb);
    cudaGetSymbolAddress(&wqb, g_wqb);
    cudaGetSymbolAddress(&wkb, g_wkb);

    cudaFuncSetAttribute(proj_kernel,   cudaFuncAttributeMaxDynamicSharedMemorySize, 57344);
    cudaFuncSetAttribute(scores_kernel, cudaFuncAttributeMaxDynamicSharedMemorySize, 104448);

    cvt_all_kernel<<<CVT_BLOCKS, 256>>>(x, qlat, Wq, Wk);

    proj_kernel<<<dim3(9, S_LEN / 128), 256, 56832>>>(
        (const __nv_bfloat16*)qlb, (const __nv_bfloat16*)wqb,
        (const __nv_bfloat16*)xb,  (const __nv_bfloat16*)wkb,
        ln_g, ln_b);

    w_kernel<<<S_LEN, 256>>>(Wwt);

    scores_kernel<<<dim3(S_LEN / 128, S_LEN / 128), 512, 104448>>>(out);
}